// round 10
// baseline (speedup 1.0000x reference)
#include <cuda_runtime.h>
#include <cstdint>

#define E_  8
#define H_  8
#define D_  512
#define B_  16
#define S_  256
#define DK_ 64

// ---------------- scratch ----------------
__device__ float g_xsum[B_ * D_];
__device__ int   g_sel[B_];
__device__ float g_qh[B_ * H_ * DK_ * S_];          // [b][h][dk][s]
__device__ float g_kh[B_ * H_ * DK_ * S_];          // [b][h][dk][kcol]
__device__ float g_vh[B_ * H_ * S_ * DK_];          // [b][h][s][dk]
__device__ float g_ctx[B_ * S_ * D_];

// ---------------- helpers ----------------
__device__ __forceinline__ uint32_t f2tf32(float x) {
    uint32_t r;
    asm("cvt.rna.tf32.f32 %0, %1;" : "=r"(r) : "f"(x));
    return r;
}

__device__ __forceinline__ void mma_tf32(float* c, const uint32_t* a, const uint32_t* b) {
    asm volatile(
        "mma.sync.aligned.m16n8k8.row.col.f32.tf32.tf32.f32 "
        "{%0,%1,%2,%3}, {%4,%5,%6,%7}, {%8,%9}, {%0,%1,%2,%3};"
        : "+f"(c[0]), "+f"(c[1]), "+f"(c[2]), "+f"(c[3])
        : "r"(a[0]), "r"(a[1]), "r"(a[2]), "r"(a[3]), "r"(b[0]), "r"(b[1]));
}

// packed fp32x2 (Blackwell FFMA2)
__device__ __forceinline__ uint64_t bcast2(float v) {
    uint64_t r;
    asm("mov.b64 %0, {%1,%1};" : "=l"(r) : "f"(v));
    return r;
}
__device__ __forceinline__ void fma2(uint64_t& c, uint64_t a, uint64_t b) {
    asm("fma.rn.f32x2 %0, %1, %2, %0;" : "+l"(c) : "l"(a), "l"(b));
}
__device__ __forceinline__ float2 unpack2(uint64_t v) {
    float2 f;
    asm("mov.b64 {%0,%1}, %2;" : "=f"(f.x), "=f"(f.y) : "l"(v));
    return f;
}
__device__ __forceinline__ float getf4(float4 v, int t) {
    switch (t) {
        case 0: return v.x;
        case 1: return v.y;
        case 2: return v.z;
        default: return v.w;
    }
}

// ---------------- threefry2x32 (JAX partitionable, key=(0,42)) ----------------
__device__ __forceinline__ uint32_t rotl32(uint32_t x, int r) {
    return (x << r) | (x >> (32 - r));
}
__device__ void threefry2x32(uint32_t k0, uint32_t k1, uint32_t c0, uint32_t c1,
                             uint32_t* o0, uint32_t* o1) {
    uint32_t ks2 = k0 ^ k1 ^ 0x1BD11BDAu;
    uint32_t x0 = c0 + k0;
    uint32_t x1 = c1 + k1;
    const int R0[4] = {13, 15, 26, 6};
    const int R1[4] = {17, 29, 16, 24};
#pragma unroll
    for (int i = 0; i < 4; i++) { x0 += x1; x1 = rotl32(x1, R0[i]); x1 ^= x0; }
    x0 += k1;  x1 += ks2 + 1u;
#pragma unroll
    for (int i = 0; i < 4; i++) { x0 += x1; x1 = rotl32(x1, R1[i]); x1 ^= x0; }
    x0 += ks2; x1 += k0 + 2u;
#pragma unroll
    for (int i = 0; i < 4; i++) { x0 += x1; x1 = rotl32(x1, R0[i]); x1 ^= x0; }
    x0 += k0;  x1 += k1 + 3u;
#pragma unroll
    for (int i = 0; i < 4; i++) { x0 += x1; x1 = rotl32(x1, R1[i]); x1 ^= x0; }
    x0 += k1;  x1 += ks2 + 4u;
#pragma unroll
    for (int i = 0; i < 4; i++) { x0 += x1; x1 = rotl32(x1, R0[i]); x1 ^= x0; }
    x0 += ks2; x1 += k0 + 5u;
    *o0 = x0; *o1 = x1;
}

__device__ float erfinv_xla(float x) {
    float w = -log1pf(-x * x);
    float p;
    if (w < 5.0f) {
        w -= 2.5f;
        p = 2.81022636e-08f;
        p = fmaf(p, w, 3.43273939e-07f);
        p = fmaf(p, w, -3.5233877e-06f);
        p = fmaf(p, w, -4.39150654e-06f);
        p = fmaf(p, w, 0.00021858087f);
        p = fmaf(p, w, -0.00125372503f);
        p = fmaf(p, w, -0.00417768164f);
        p = fmaf(p, w, 0.246640727f);
        p = fmaf(p, w, 1.50140941f);
    } else {
        w = sqrtf(w) - 3.0f;
        p = -0.000200214257f;
        p = fmaf(p, w, 0.000100950558f);
        p = fmaf(p, w, 0.00134934322f);
        p = fmaf(p, w, -0.00367342844f);
        p = fmaf(p, w, 0.00573950773f);
        p = fmaf(p, w, -0.0076224613f);
        p = fmaf(p, w, 0.00943887047f);
        p = fmaf(p, w, 1.00167406f);
        p = fmaf(p, w, 2.83297682f);
    }
    return p * x;
}

// ---------------- K1: full xsum ----------------
__global__ void xsum_kernel(const float* __restrict__ q) {
    int b = blockIdx.x, d = threadIdx.x;
    const float* p = q + (size_t)b * S_ * D_ + d;
    float acc = 0.0f;
#pragma unroll 16
    for (int s = 0; s < S_; s++) acc += p[s * D_];
    g_xsum[b * D_ + d] = acc;
}

// ---------------- K2: gating (1024 threads, sliced dot products) ----------------
__global__ __launch_bounds__(1024) void gating_kernel(const float* __restrict__ wg,
                                                      const float* __restrict__ wn,
                                                      float* __restrict__ d_out,
                                                      int out_size) {
    int tid = threadIdx.x;
    int be = tid & 127, slice = tid >> 7;
    int b = be >> 3, e = be & 7;

    float clp = 0.0f, rnp = 0.0f;
#pragma unroll 8
    for (int i = slice * 64; i < slice * 64 + 64; i++) {
        float xs = g_xsum[b * D_ + i];
        clp = fmaf(xs, wg[i * E_ + e], clp);
        rnp = fmaf(xs, wn[i * E_ + e], rnp);
    }

    __shared__ float scl[8][128], srn[8][128];
    __shared__ float s_noisy[128], s_thrin[B_], s_throut[B_];
    __shared__ float s_load[E_], s_imp[E_];
    scl[slice][be] = clp; srn[slice][be] = rnp;
    if (tid < E_) { s_load[tid] = 0.0f; s_imp[tid] = 0.0f; }
    __syncthreads();

    float cl = 0.0f, rn = 0.0f, stdv = 1.0f, noisy = 0.0f;
    if (tid < 128) {
#pragma unroll
        for (int s = 0; s < 8; s++) { cl += scl[s][tid]; rn += srn[s][tid]; }

        float sp = fmaxf(rn, 0.0f) + log1pf(expf(-fabsf(rn)));
        stdv = sp + 0.01f;

        uint32_t o0, o1;
        threefry2x32(0u, 42u, 0u, (uint32_t)tid, &o0, &o1);
        uint32_t bits = o0 ^ o1;
        uint32_t fb = (bits >> 9) | 0x3f800000u;
        float f = __uint_as_float(fb) - 1.0f;
        float u = f * 2.0f + (-0.99999994f);
        u = fmaxf(-0.99999994f, u);
        float z = 1.41421354f * erfinv_xla(u);
        noisy = cl + z * stdv;
        s_noisy[tid] = noisy;
    }
    __syncthreads();

    if (tid < B_) {
        float m1 = -3.0e38f, m2 = -3.0e38f;
        int i1 = 0;
        for (int ee = 0; ee < E_; ee++) {
            float val = s_noisy[tid * 8 + ee];
            if (val > m1) { m2 = m1; m1 = val; i1 = ee; }
            else if (val > m2) { m2 = val; }
        }
        g_sel[tid] = i1;
        s_thrin[tid] = m2;
        s_throut[tid] = m1;
        atomicAdd(&s_imp[i1], 1.0f);
    }
    __syncthreads();

    if (tid < 128) {
        float thr = (noisy > s_thrin[b]) ? s_thrin[b] : s_throut[b];
        float arg = ((cl - thr) / stdv) / 1.41421354f;
        float ph = 0.5f * (1.0f + erff(arg));
        atomicAdd(&s_load[e], ph);
    }
    __syncthreads();

    if (tid == 0) {
        auto cv2 = [](const float* x) {
            float mean = 0.0f;
            for (int i = 0; i < E_; i++) mean += x[i];
            mean *= (1.0f / E_);
            float var = 0.0f;
            for (int i = 0; i < E_; i++) { float d = x[i] - mean; var += d * d; }
            var *= (1.0f / (E_ - 1));
            return var / (mean * mean + 1e-10f);
        };
        float loss = 0.01f * (cv2(s_imp) + cv2(s_load));
        if (out_size > B_ * S_ * D_) d_out[B_ * S_ * D_] = loss;
    }
}

// ---------------- tf32 mma.sync mainloop (128x128 block, K=512) ----------------
// Fragment-permuted smem: A bufs @0/@4096 (float4 per (wmhalf,mt,ks,lane)),
// B bufs @8192/@12288 (float2 per (wnidx,nt,ks,lane)). Each buffer 16 KB.
#define MMA_SMEM_BYTES (16384 * 4)

__device__ __forceinline__ void stage_A(uint32_t* dst, const float4* ar,
                                        int arow, int acol) {
    const int wmhalf = arow >> 6, mt = (arow >> 4) & 3;
    const int half8 = (arow >> 3) & 1, grp = arow & 7;
#pragma unroll
    for (int i = 0; i < 4; i++) {
        float vals[4] = {ar[i].x, ar[i].y, ar[i].z, ar[i].w};
#pragma unroll
        for (int jj = 0; jj < 4; jj++) {
            int k = acol + 4 * i + jj;
            int ks = k >> 3, tig = k & 3, khalf = (k >> 2) & 1;
            int lane = grp * 4 + tig;
            int comp = half8 + 2 * khalf;
            dst[((((wmhalf * 4 + mt) * 4 + ks) * 32 + lane) << 2) + comp] = f2tf32(vals[jj]);
        }
    }
}

__device__ __forceinline__ void stage_B(uint32_t* dst, const float4* br,
                                        int brow, int bcol) {
    const int ks = brow >> 3, tig = brow & 3, khalf = (brow >> 2) & 1;
#pragma unroll
    for (int i = 0; i < 4; i++) {
        float vals[4] = {br[i].x, br[i].y, br[i].z, br[i].w};
#pragma unroll
        for (int jj = 0; jj < 4; jj++) {
            int n = bcol + 4 * i + jj;
            int lane = (n & 7) * 4 + tig;
            dst[((((((n >> 5) * 4) + ((n >> 3) & 3)) * 4 + ks) * 32 + lane) << 1) + khalf] =
                f2tf32(vals[jj]);
        }
    }
}

__device__ __forceinline__ void mma_mainloop(
        uint32_t* sm, const float* __restrict__ A, int lda,
        const float* __restrict__ W, int n0, float acc[4][4][4]) {
    const int tid = threadIdx.x;
    const int wid = tid >> 5, lane = tid & 31;
    const int wmhalf = wid & 1, wnidx = wid >> 1;

    const int arow = tid >> 1, acol = (tid & 1) * 16;
    const int brow = tid >> 3, bcol = (tid & 7) * 16;

    float4 ar[4], br[4];
#pragma unroll
    for (int i = 0; i < 4; i++) {
        ar[i] = *(const float4*)(A + (size_t)arow * lda + acol + 4 * i);
        br[i] = *(const float4*)(W + (size_t)brow * D_ + n0 + bcol + 4 * i);
    }
    stage_A(sm, ar, arow, acol);
    stage_B(sm + 8192, br, brow, bcol);
    __syncthreads();

    for (int t = 0; t < 16; t++) {
        int buf = t & 1;
        if (t < 15) {
            int kb = (t + 1) * 32;
#pragma unroll
            for (int i = 0; i < 4; i++) {
                ar[i] = *(const float4*)(A + (size_t)arow * lda + kb + acol + 4 * i);
                br[i] = *(const float4*)(W + (size_t)(kb + brow) * D_ + n0 + bcol + 4 * i);
            }
        }
        const uint32_t* As = sm + buf * 4096;
        const uint32_t* Bs = sm + 8192 + buf * 4096;
#pragma unroll
        for (int ks = 0; ks < 4; ks++) {
            uint32_t af[4][4], bf[4][2];
#pragma unroll
            for (int mt = 0; mt < 4; mt++) {
                uint4 v = *(const uint4*)&As[(((wmhalf * 4 + mt) * 4 + ks) * 32 + lane) << 2];
                af[mt][0] = v.x; af[mt][1] = v.y; af[mt][2] = v.z; af[mt][3] = v.w;
            }
#pragma unroll
            for (int nt = 0; nt < 4; nt++) {
                uint2 v = *(const uint2*)&Bs[(((wnidx * 4 + nt) * 4 + ks) * 32 + lane) << 1];
                bf[nt][0] = v.x; bf[nt][1] = v.y;
            }
#pragma unroll
            for (int mt = 0; mt < 4; mt++)
#pragma unroll
                for (int nt = 0; nt < 4; nt++)
                    mma_tf32(acc[mt][nt], af[mt], bf[nt]);
        }
        if (t < 15) {
            int nb = buf ^ 1;
            stage_A(sm + nb * 4096, ar, arow, acol);
            stage_B(sm + 8192 + nb * 4096, br, brow, bcol);
            __syncthreads();
        }
    }
}

// ---------------- K3: projections via mma.sync tf32 ----------------
__global__ __launch_bounds__(256, 2) void proj_mma(
        const float* __restrict__ q, const float* __restrict__ k,
        const float* __restrict__ v,
        const float* __restrict__ wq, const float* __restrict__ wk,
        const float* __restrict__ wv,
        const float* __restrict__ bq, const float* __restrict__ bk,
        const float* __restrict__ bv) {
    extern __shared__ uint32_t smu[];
    int z = blockIdx.z;
    int b = z / 3, p = z % 3;
    int e = g_sel[b];
    const float* X = (p == 0 ? q : (p == 1 ? k : v)) + (size_t)b * S_ * D_;
    const float* W = (p == 0 ? wq : (p == 1 ? wk : wv)) + (size_t)e * D_ * D_;
    const float* bias = (p == 0 ? bq : (p == 1 ? bk : bv)) + e * D_;
    float* Out = (p == 0 ? g_qh : (p == 1 ? g_kh : g_vh));
    int bn = blockIdx.x * 128, m0 = blockIdx.y * 128;

    float acc[4][4][4] = {};
    mma_mainloop(smu, X + (size_t)m0 * D_, D_, W, bn, acc);

    const int lane = threadIdx.x & 31, wid = threadIdx.x >> 5;
    const int wm = (wid & 1) * 64, wn = (wid >> 1) * 32;
    const int group = lane >> 2, tig = lane & 3;

#pragma unroll
    for (int mt = 0; mt < 4; mt++) {
#pragma unroll
        for (int nt = 0; nt < 4; nt++) {
            int n = bn + wn + nt * 8 + 2 * tig;
            int m = m0 + wm + mt * 16 + group;
            int h = n >> 6, dk = n & 63;
            float b0v = bias[n], b1v = bias[n + 1];
            if (p < 2) {
                size_t base = ((size_t)(b * H_ + h) * DK_ + dk) * S_;
                Out[base + m]            = acc[mt][nt][0] + b0v;
                Out[base + S_ + m]       = acc[mt][nt][1] + b1v;
                Out[base + m + 8]        = acc[mt][nt][2] + b0v;
                Out[base + S_ + m + 8]   = acc[mt][nt][3] + b1v;
            } else {
                size_t base = ((size_t)(b * H_ + h) * S_ + m) * DK_ + dk;
                Out[base]                = acc[mt][nt][0] + b0v;
                Out[base + 1]            = acc[mt][nt][1] + b1v;
                Out[base + 8 * DK_]      = acc[mt][nt][2] + b0v;
                Out[base + 8 * DK_ + 1]  = acc[mt][nt][3] + b1v;
            }
        }
    }
}

// ---------------- K5: final projection via mma.sync tf32 ----------------
__global__ __launch_bounds__(256, 2) void final_mma(const float* __restrict__ wo,
                                                    const float* __restrict__ bo,
                                                    float* __restrict__ out) {
    extern __shared__ uint32_t smu[];
    int b = blockIdx.z;
    int e = g_sel[b];
    const float* A = g_ctx + (size_t)b * S_ * D_;
    const float* W = wo + (size_t)e * D_ * D_;
    const float* bias = bo + e * D_;
    int bn = blockIdx.x * 128, m0 = blockIdx.y * 128;

    float acc[4][4][4] = {};
    mma_mainloop(smu, A + (size_t)m0 * D_, D_, W, bn, acc);

    const int lane = threadIdx.x & 31, wid = threadIdx.x >> 5;
    const int wm = (wid & 1) * 64, wn = (wid >> 1) * 32;
    const int group = lane >> 2, tig = lane & 3;

#pragma unroll
    for (int mt = 0; mt < 4; mt++) {
#pragma unroll
        for (int nt = 0; nt < 4; nt++) {
            int n = bn + wn + nt * 8 + 2 * tig;
            int m = m0 + wm + mt * 16 + group;
            float b0v = bias[n], b1v = bias[n + 1];
            float* d0 = out + ((size_t)b * S_ + m) * D_ + n;
            d0[0]            = acc[mt][nt][0] + b0v;
            d0[1]            = acc[mt][nt][1] + b1v;
            d0[8 * D_]       = acc[mt][nt][2] + b0v;
            d0[8 * D_ + 1]   = acc[mt][nt][3] + b1v;
        }
    }
}

// ---------------- K4: fused attention, 512 blocks (b,h,qt), streamed K/V ----------------
// smem floats: Qt[64dk][64q] @0 | Buf0 @4096 | Buf1 @8192 (each 64x64) | Ps[64q][256] @12288
#define ATTN_SMEM_BYTES (28672 * 4)

__global__ __launch_bounds__(256, 2) void fused_attn_kernel(const int* __restrict__ mask) {
    extern __shared__ float smf[];
    float* Qt = smf;
    float* Ps = smf + 12288;

    int z = blockIdx.x;                 // 512 blocks
    int bh = z >> 2, qt = z & 3;
    int b = bh >> 3, h = bh & 7;
    int tid = threadIdx.x;
    int warp = tid >> 5, lane = tid & 31;

    const float* ksrc = g_kh + (size_t)bh * 16384;   // [dk][256]
    const float* vsrc = g_vh + (size_t)bh * 16384;   // [256][64]
    const float* qsrc = g_qh + (size_t)bh * 16384 + qt * 64;

    // load Qt[dk][0..63]
    {
#pragma unroll
        for (int j = 0; j < 4; j++) {
            int lin = tid + j * 256;
            int dk = lin >> 4, c = (lin & 15) * 4;
            *(float4*)&Qt[dk * 64 + c] = *(const float4*)(qsrc + (size_t)dk * S_ + c);
        }
    }

    // preload K chunk 0 into Buf0
    {
        float* dst = smf + 4096;
#pragma unroll
        for (int j = 0; j < 4; j++) {
            int lin = tid + j * 256;
            int dk = lin >> 4, c = (lin & 15) * 4;
            *(float4*)&dst[dk * 64 + c] = *(const float4*)(ksrc + (size_t)dk * S_ + c);
        }
    }
    __syncthreads();

    // -------- GEMM1: scores over 4 K-chunks --------
    float pf[8][8];
    for (int ch = 0; ch < 4; ch++) {
        float4 nx[4];
        if (ch < 3) {
#pragma unroll
            for (int j = 0; j < 4; j++) {
                int lin = tid + j * 256;
                int dk = lin >> 4, c = (lin & 15) * 4;
                nx[j] = *(const float4*)(ksrc + (size_t)dk * S_ + (ch + 1) * 64 + c);
            }
        }
        const float* cur = smf + 4096 + (ch & 1) * 4096;

        uint64_t pch[8] = {};
        {
            float4 x0 = *(const float4*)&Qt[warp * 8];
            float4 x1 = *(const float4*)&Qt[warp * 8 + 4];
            uint64_t kk = *(const uint64_t*)&cur[lane * 2];
#pragma unroll 8
            for (int dk = 0; dk < 64; dk++) {
                float a[8] = {x0.x, x0.y, x0.z, x0.w, x1.x, x1.y, x1.z, x1.w};
                uint64_t kc = kk;
                if (dk < 63) {
                    x0 = *(const float4*)&Qt[(dk + 1) * 64 + warp * 8];
                    x1 = *(const float4*)&Qt[(dk + 1) * 64 + warp * 8 + 4];
                    kk = *(const uint64_t*)&cur[(dk + 1) * 64 + lane * 2];
                }
#pragma unroll
                for (int i = 0; i < 8; i++) fma2(pch[i], bcast2(a[i]), kc);
            }
        }
#pragma unroll
        for (int i = 0; i < 8; i++) {
            float2 f = unpack2(pch[i]);
            pf[i][2 * ch]     = f.x;
            pf[i][2 * ch + 1] = f.y;
        }

        if (ch < 3) {
            float* nb = smf + 4096 + ((ch + 1) & 1) * 4096;
#pragma unroll
            for (int j = 0; j < 4; j++) {
                int lin = tid + j * 256;
                int dk = lin >> 4, c = (lin & 15) * 4;
                *(float4*)&nb[dk * 64 + c] = nx[j];
            }
        }
        __syncthreads();
    }

    // -------- mask + softmax (row = warp; lane owns cols ch*64+lane*2+{0,1}) --------
#pragma unroll
    for (int i = 0; i < 8; i++) {
        int r = qt * 64 + warp * 8 + i;
#pragma unroll
        for (int c = 0; c < 4; c++) {
            int2 mm = *(const int2*)&mask[r * S_ + c * 64 + lane * 2];
            pf[i][2 * c]     = (mm.x == 0) ? -1e9f : pf[i][2 * c]     * 0.125f;
            pf[i][2 * c + 1] = (mm.y == 0) ? -1e9f : pf[i][2 * c + 1] * 0.125f;
        }
        float mx = pf[i][0];
#pragma unroll
        for (int j = 1; j < 8; j++) mx = fmaxf(mx, pf[i][j]);
#pragma unroll
        for (int off = 16; off > 0; off >>= 1)
            mx = fmaxf(mx, __shfl_xor_sync(0xffffffffu, mx, off));
        float sum = 0.0f;
#pragma unroll
        for (int j = 0; j < 8; j++) { pf[i][j] = __expf(pf[i][j] - mx); sum += pf[i][j]; }
#pragma unroll
        for (int off = 16; off > 0; off >>= 1)
            sum += __shfl_xor_sync(0xffffffffu, sum, off);
        float inv = 1.0f / sum;
#pragma unroll
        for (int j = 0; j < 8; j++) pf[i][j] *= inv;
    }

    // write Ps[row][col]
#pragma unroll
    for (int i = 0; i < 8; i++) {
        int row = warp * 8 + i;
#pragma unroll
        for (int c = 0; c < 4; c++) {
            *(float2*)&Ps[row * 256 + c * 64 + lane * 2] =
                make_float2(pf[i][2 * c], pf[i][2 * c + 1]);
        }
    }

    // preload V chunk 0 into Buf0 (contiguous copy)
    {
        float4* dst = (float4*)(smf + 4096);
        const float4* src = (const float4*)vsrc;
#pragma unroll
        for (int j = 0; j < 4; j++) dst[tid + j * 256] = src[tid + j * 256];
    }
    __syncthreads();

    // -------- GEMM2: ctx = Ps @ V over 4 V-chunks --------
    const int ty2 = tid >> 4, tx2 = tid & 15;
    uint64_t c2p[4][2] = {};
    for (int ch = 0; ch < 4; ch++) {
        float4 nv[4];
        if (ch < 3) {
            const float4* src = (const float4*)(vsrc + (ch + 1) * 4096);
#pragma unroll
            for (int j = 0; j < 4; j++) nv[j] = src[tid + j * 256];
        }
        const float* Vb = smf + 4096 + (ch & 1) * 4096;   // [64 rows][64 dk]

        {
            float4 av[2][4];
            uint64_t bvu[2][4][2];
#pragma unroll
            for (int i = 0; i < 4; i++)
                av[0][i] = *(const float4*)&Ps[(ty2 * 4 + i) * 256 + ch * 64];
#pragma unroll
            for (int t = 0; t < 4; t++) {
                const uint64_t* vp = (const uint64_t*)&Vb[t * 64 + tx2 * 4];
                bvu[0][t][0] = vp[0]; bvu[0][t][1] = vp[1];
            }
#pragma unroll 2
            for (int kc = 0; kc < 64; kc += 4) {
                int curb = (kc >> 2) & 1, nxt = curb ^ 1;
                if (kc < 60) {
#pragma unroll
                    for (int i = 0; i < 4; i++)
                        av[nxt][i] = *(const float4*)&Ps[(ty2 * 4 + i) * 256 + ch * 64 + kc + 4];
#pragma unroll
                    for (int t = 0; t < 4; t++) {
                        const uint64_t* vp = (const uint64_t*)&Vb[(kc + 4 + t) * 64 + tx2 * 4];
                        bvu[nxt][t][0] = vp[0]; bvu[nxt][t][1] = vp[1];
                    }
                }
#pragma unroll
                for (int t = 0; t < 4; t++) {
#pragma unroll
                    for (int i = 0; i < 4; i++) {
                        uint64_t ap = bcast2(getf4(av[curb][i], t));
                        fma2(c2p[i][0], ap, bvu[curb][t][0]);
                        fma2(c2p[i][1], ap, bvu[curb][t][1]);
                    }
                }
            }
        }

        if (ch < 3) {
            float* nb = smf + 4096 + ((ch + 1) & 1) * 4096;
            float4* dst = (float4*)nb;
#pragma unroll
            for (int j = 0; j < 4; j++) dst[tid + j * 256] = nv[j];
        }
        __syncthreads();
    }

    // write ctx
#pragma unroll
    for (int i = 0; i < 4; i++) {
        int s = qt * 64 + ty2 * 4 + i;
        float2 lo = unpack2(c2p[i][0]);
        float2 hi = unpack2(c2p[i][1]);
        *(float4*)&g_ctx[((size_t)b * S_ + s) * D_ + h * DK_ + tx2 * 4] =
            make_float4(lo.x, lo.y, hi.x, hi.y);
    }
}

// ---------------- launch ----------------
extern "C" void kernel_launch(void* const* d_in, const int* in_sizes, int n_in,
                              void* d_out, int out_size) {
    const float* q    = (const float*)d_in[0];
    const float* k    = (const float*)d_in[1];
    const float* v    = (const float*)d_in[2];
    const int*   mask = (const int*)  d_in[3];
    const float* wg   = (const float*)d_in[4];
    const float* wn   = (const float*)d_in[5];
    const float* wq   = (const float*)d_in[6];
    const float* bq   = (const float*)d_in[7];
    const float* wk   = (const float*)d_in[8];
    const float* bk   = (const float*)d_in[9];
    const float* wv   = (const float*)d_in[10];
    const float* bv   = (const float*)d_in[11];
    const float* wo   = (const float*)d_in[12];
    const float* bo   = (const float*)d_in[13];
    float* out = (float*)d_out;

    cudaFuncSetAttribute(fused_attn_kernel,
                         cudaFuncAttributeMaxDynamicSharedMemorySize, ATTN_SMEM_BYTES);
    cudaFuncSetAttribute(proj_mma,
                         cudaFuncAttributeMaxDynamicSharedMemorySize, MMA_SMEM_BYTES);
    cudaFuncSetAttribute(final_mma,
                         cudaFuncAttributeMaxDynamicSharedMemorySize, MMA_SMEM_BYTES);

    xsum_kernel<<<B_, 512>>>(q);
    gating_kernel<<<1, 1024>>>(wg, wn, out, out_size);
    proj_mma<<<dim3(4, 2, B_ * 3), 256, MMA_SMEM_BYTES>>>(q, k, v, wq, wk, wv, bq, bk, bv);
    fused_attn_kernel<<<B_ * H_ * 4, 256, ATTN_SMEM_BYTES>>>(mask);
    final_mma<<<dim3(4, 2, B_), 256, MMA_SMEM_BYTES>>>(wo, bo, out);
}

// round 11
// speedup vs baseline: 1.0625x; 1.0625x over previous
#include <cuda_runtime.h>
#include <cstdint>

#define E_  8
#define H_  8
#define D_  512
#define B_  16
#define S_  256
#define DK_ 64

// ---------------- scratch ----------------
__device__ float g_xsum[B_ * D_];
__device__ int   g_sel[B_];
__device__ float g_qh[B_ * H_ * DK_ * S_];          // [b][h][dk][s]
__device__ float g_kh[B_ * H_ * DK_ * S_];          // [b][h][dk][kcol]
__device__ float g_vh[B_ * H_ * S_ * DK_];          // [b][h][s][dk]
__device__ float g_ctx[B_ * S_ * D_];

// ---------------- helpers ----------------
__device__ __forceinline__ uint32_t f2tf32(float x) {
    uint32_t r;
    asm("cvt.rna.tf32.f32 %0, %1;" : "=r"(r) : "f"(x));
    return r;
}

__device__ __forceinline__ void mma_tf32(float* c, const uint32_t* a, const uint32_t* b) {
    asm volatile(
        "mma.sync.aligned.m16n8k8.row.col.f32.tf32.tf32.f32 "
        "{%0,%1,%2,%3}, {%4,%5,%6,%7}, {%8,%9}, {%0,%1,%2,%3};"
        : "+f"(c[0]), "+f"(c[1]), "+f"(c[2]), "+f"(c[3])
        : "r"(a[0]), "r"(a[1]), "r"(a[2]), "r"(a[3]), "r"(b[0]), "r"(b[1]));
}

// packed fp32x2 (Blackwell FFMA2)
__device__ __forceinline__ uint64_t bcast2(float v) {
    uint64_t r;
    asm("mov.b64 %0, {%1,%1};" : "=l"(r) : "f"(v));
    return r;
}
__device__ __forceinline__ void fma2(uint64_t& c, uint64_t a, uint64_t b) {
    asm("fma.rn.f32x2 %0, %1, %2, %0;" : "+l"(c) : "l"(a), "l"(b));
}
__device__ __forceinline__ float2 unpack2(uint64_t v) {
    float2 f;
    asm("mov.b64 {%0,%1}, %2;" : "=f"(f.x), "=f"(f.y) : "l"(v));
    return f;
}
__device__ __forceinline__ float getf4(float4 v, int t) {
    switch (t) {
        case 0: return v.x;
        case 1: return v.y;
        case 2: return v.z;
        default: return v.w;
    }
}

// ---------------- threefry2x32 (JAX partitionable, key=(0,42)) ----------------
__device__ __forceinline__ uint32_t rotl32(uint32_t x, int r) {
    return (x << r) | (x >> (32 - r));
}
__device__ void threefry2x32(uint32_t k0, uint32_t k1, uint32_t c0, uint32_t c1,
                             uint32_t* o0, uint32_t* o1) {
    uint32_t ks2 = k0 ^ k1 ^ 0x1BD11BDAu;
    uint32_t x0 = c0 + k0;
    uint32_t x1 = c1 + k1;
    const int R0[4] = {13, 15, 26, 6};
    const int R1[4] = {17, 29, 16, 24};
#pragma unroll
    for (int i = 0; i < 4; i++) { x0 += x1; x1 = rotl32(x1, R0[i]); x1 ^= x0; }
    x0 += k1;  x1 += ks2 + 1u;
#pragma unroll
    for (int i = 0; i < 4; i++) { x0 += x1; x1 = rotl32(x1, R1[i]); x1 ^= x0; }
    x0 += ks2; x1 += k0 + 2u;
#pragma unroll
    for (int i = 0; i < 4; i++) { x0 += x1; x1 = rotl32(x1, R0[i]); x1 ^= x0; }
    x0 += k0;  x1 += k1 + 3u;
#pragma unroll
    for (int i = 0; i < 4; i++) { x0 += x1; x1 = rotl32(x1, R1[i]); x1 ^= x0; }
    x0 += k1;  x1 += ks2 + 4u;
#pragma unroll
    for (int i = 0; i < 4; i++) { x0 += x1; x1 = rotl32(x1, R0[i]); x1 ^= x0; }
    x0 += ks2; x1 += k0 + 5u;
    *o0 = x0; *o1 = x1;
}

__device__ float erfinv_xla(float x) {
    float w = -log1pf(-x * x);
    float p;
    if (w < 5.0f) {
        w -= 2.5f;
        p = 2.81022636e-08f;
        p = fmaf(p, w, 3.43273939e-07f);
        p = fmaf(p, w, -3.5233877e-06f);
        p = fmaf(p, w, -4.39150654e-06f);
        p = fmaf(p, w, 0.00021858087f);
        p = fmaf(p, w, -0.00125372503f);
        p = fmaf(p, w, -0.00417768164f);
        p = fmaf(p, w, 0.246640727f);
        p = fmaf(p, w, 1.50140941f);
    } else {
        w = sqrtf(w) - 3.0f;
        p = -0.000200214257f;
        p = fmaf(p, w, 0.000100950558f);
        p = fmaf(p, w, 0.00134934322f);
        p = fmaf(p, w, -0.00367342844f);
        p = fmaf(p, w, 0.00573950773f);
        p = fmaf(p, w, -0.0076224613f);
        p = fmaf(p, w, 0.00943887047f);
        p = fmaf(p, w, 1.00167406f);
        p = fmaf(p, w, 2.83297682f);
    }
    return p * x;
}

// ---------------- K1: full xsum ----------------
__global__ void xsum_kernel(const float* __restrict__ q) {
    int b = blockIdx.x, d = threadIdx.x;
    const float* p = q + (size_t)b * S_ * D_ + d;
    float acc = 0.0f;
#pragma unroll 16
    for (int s = 0; s < S_; s++) acc += p[s * D_];
    g_xsum[b * D_ + d] = acc;
}

// ---------------- K2: gating (1024 threads, sliced dot products) ----------------
__global__ __launch_bounds__(1024) void gating_kernel(const float* __restrict__ wg,
                                                      const float* __restrict__ wn,
                                                      float* __restrict__ d_out,
                                                      int out_size) {
    int tid = threadIdx.x;
    int be = tid & 127, slice = tid >> 7;
    int b = be >> 3, e = be & 7;

    float clp = 0.0f, rnp = 0.0f;
#pragma unroll 8
    for (int i = slice * 64; i < slice * 64 + 64; i++) {
        float xs = g_xsum[b * D_ + i];
        clp = fmaf(xs, wg[i * E_ + e], clp);
        rnp = fmaf(xs, wn[i * E_ + e], rnp);
    }

    __shared__ float scl[8][128], srn[8][128];
    __shared__ float s_noisy[128], s_thrin[B_], s_throut[B_];
    __shared__ float s_load[E_], s_imp[E_];
    scl[slice][be] = clp; srn[slice][be] = rnp;
    if (tid < E_) { s_load[tid] = 0.0f; s_imp[tid] = 0.0f; }
    __syncthreads();

    float cl = 0.0f, rn = 0.0f, stdv = 1.0f, noisy = 0.0f;
    if (tid < 128) {
#pragma unroll
        for (int s = 0; s < 8; s++) { cl += scl[s][tid]; rn += srn[s][tid]; }

        float sp = fmaxf(rn, 0.0f) + log1pf(expf(-fabsf(rn)));
        stdv = sp + 0.01f;

        uint32_t o0, o1;
        threefry2x32(0u, 42u, 0u, (uint32_t)tid, &o0, &o1);
        uint32_t bits = o0 ^ o1;
        uint32_t fb = (bits >> 9) | 0x3f800000u;
        float f = __uint_as_float(fb) - 1.0f;
        float u = f * 2.0f + (-0.99999994f);
        u = fmaxf(-0.99999994f, u);
        float z = 1.41421354f * erfinv_xla(u);
        noisy = cl + z * stdv;
        s_noisy[tid] = noisy;
    }
    __syncthreads();

    if (tid < B_) {
        float m1 = -3.0e38f, m2 = -3.0e38f;
        int i1 = 0;
        for (int ee = 0; ee < E_; ee++) {
            float val = s_noisy[tid * 8 + ee];
            if (val > m1) { m2 = m1; m1 = val; i1 = ee; }
            else if (val > m2) { m2 = val; }
        }
        g_sel[tid] = i1;
        s_thrin[tid] = m2;
        s_throut[tid] = m1;
        atomicAdd(&s_imp[i1], 1.0f);
    }
    __syncthreads();

    if (tid < 128) {
        float thr = (noisy > s_thrin[b]) ? s_thrin[b] : s_throut[b];
        float arg = ((cl - thr) / stdv) / 1.41421354f;
        float ph = 0.5f * (1.0f + erff(arg));
        atomicAdd(&s_load[e], ph);
    }
    __syncthreads();

    if (tid == 0) {
        auto cv2 = [](const float* x) {
            float mean = 0.0f;
            for (int i = 0; i < E_; i++) mean += x[i];
            mean *= (1.0f / E_);
            float var = 0.0f;
            for (int i = 0; i < E_; i++) { float d = x[i] - mean; var += d * d; }
            var *= (1.0f / (E_ - 1));
            return var / (mean * mean + 1e-10f);
        };
        float loss = 0.01f * (cv2(s_imp) + cv2(s_load));
        if (out_size > B_ * S_ * D_) d_out[B_ * S_ * D_] = loss;
    }
}

// ---------------- tf32 mma.sync mainloop (128x128 block, K=512) — R9 version ----------------
#define SA_ 36
#define SB_ 132
#define MMA_SMEM_BYTES ((4608 * 2 + 4224 * 2) * 4)

__device__ __forceinline__ void mma_mainloop(
        uint32_t* sm, const float* __restrict__ A, int lda,
        const float* __restrict__ W, int n0, float acc[4][4][4]) {
    const int tid = threadIdx.x;
    const int wid = tid >> 5, lane = tid & 31;
    const int wm = (wid & 1) * 64, wn = (wid >> 1) * 32;
    const int group = lane >> 2, tig = lane & 3;

    const int arow = tid >> 1, acol = (tid & 1) * 16;
    const int brow = tid >> 3, bcol = (tid & 7) * 16;

    float4 ar[4], br[4];
#pragma unroll
    for (int i = 0; i < 4; i++) {
        ar[i] = *(const float4*)(A + (size_t)arow * lda + acol + 4 * i);
        br[i] = *(const float4*)(W + (size_t)brow * D_ + n0 + bcol + 4 * i);
    }
    {
        uint32_t* da = sm + arow * SA_ + acol;
        uint32_t* db = sm + 9216 + brow * SB_ + bcol;
#pragma unroll
        for (int i = 0; i < 4; i++) {
            da[4*i+0] = f2tf32(ar[i].x); da[4*i+1] = f2tf32(ar[i].y);
            da[4*i+2] = f2tf32(ar[i].z); da[4*i+3] = f2tf32(ar[i].w);
            db[4*i+0] = f2tf32(br[i].x); db[4*i+1] = f2tf32(br[i].y);
            db[4*i+2] = f2tf32(br[i].z); db[4*i+3] = f2tf32(br[i].w);
        }
    }
    __syncthreads();

    for (int t = 0; t < 16; t++) {
        int buf = t & 1;
        if (t < 15) {
            int kb = (t + 1) * 32;
#pragma unroll
            for (int i = 0; i < 4; i++) {
                ar[i] = *(const float4*)(A + (size_t)arow * lda + kb + acol + 4 * i);
                br[i] = *(const float4*)(W + (size_t)(kb + brow) * D_ + n0 + bcol + 4 * i);
            }
        }
        uint32_t* As = sm + buf * 4608;
        uint32_t* Bs = sm + 9216 + buf * 4224;
#pragma unroll
        for (int ks = 0; ks < 4; ks++) {
            int k0 = ks * 8;
            uint32_t af[4][4], bf[4][2];
#pragma unroll
            for (int mt = 0; mt < 4; mt++) {
                int r0 = wm + mt * 16 + group;
                af[mt][0] = As[r0 * SA_ + k0 + tig];
                af[mt][1] = As[(r0 + 8) * SA_ + k0 + tig];
                af[mt][2] = As[r0 * SA_ + k0 + tig + 4];
                af[mt][3] = As[(r0 + 8) * SA_ + k0 + tig + 4];
            }
#pragma unroll
            for (int nt = 0; nt < 4; nt++) {
                int c0 = wn + nt * 8 + group;
                bf[nt][0] = Bs[(k0 + tig) * SB_ + c0];
                bf[nt][1] = Bs[(k0 + tig + 4) * SB_ + c0];
            }
#pragma unroll
            for (int mt = 0; mt < 4; mt++)
#pragma unroll
                for (int nt = 0; nt < 4; nt++)
                    mma_tf32(acc[mt][nt], af[mt], bf[nt]);
        }
        if (t < 15) {
            int nb = buf ^ 1;
            uint32_t* da = sm + nb * 4608 + arow * SA_ + acol;
            uint32_t* db = sm + 9216 + nb * 4224 + brow * SB_ + bcol;
#pragma unroll
            for (int i = 0; i < 4; i++) {
                da[4*i+0] = f2tf32(ar[i].x); da[4*i+1] = f2tf32(ar[i].y);
                da[4*i+2] = f2tf32(ar[i].z); da[4*i+3] = f2tf32(ar[i].w);
                db[4*i+0] = f2tf32(br[i].x); db[4*i+1] = f2tf32(br[i].y);
                db[4*i+2] = f2tf32(br[i].z); db[4*i+3] = f2tf32(br[i].w);
            }
            __syncthreads();
        }
    }
}

// ---------------- K3: projections via mma.sync tf32 ----------------
__global__ __launch_bounds__(256) void proj_mma(
        const float* __restrict__ q, const float* __restrict__ k,
        const float* __restrict__ v,
        const float* __restrict__ wq, const float* __restrict__ wk,
        const float* __restrict__ wv,
        const float* __restrict__ bq, const float* __restrict__ bk,
        const float* __restrict__ bv) {
    extern __shared__ uint32_t smu[];
    int z = blockIdx.z;
    int b = z / 3, p = z % 3;
    int e = g_sel[b];
    const float* X = (p == 0 ? q : (p == 1 ? k : v)) + (size_t)b * S_ * D_;
    const float* W = (p == 0 ? wq : (p == 1 ? wk : wv)) + (size_t)e * D_ * D_;
    const float* bias = (p == 0 ? bq : (p == 1 ? bk : bv)) + e * D_;
    float* Out = (p == 0 ? g_qh : (p == 1 ? g_kh : g_vh));
    int bn = blockIdx.x * 128, m0 = blockIdx.y * 128;

    float acc[4][4][4] = {};
    mma_mainloop(smu, X + (size_t)m0 * D_, D_, W, bn, acc);

    const int lane = threadIdx.x & 31, wid = threadIdx.x >> 5;
    const int wm = (wid & 1) * 64, wn = (wid >> 1) * 32;
    const int group = lane >> 2, tig = lane & 3;

#pragma unroll
    for (int mt = 0; mt < 4; mt++) {
#pragma unroll
        for (int nt = 0; nt < 4; nt++) {
            int n = bn + wn + nt * 8 + 2 * tig;
            int m = m0 + wm + mt * 16 + group;
            int h = n >> 6, dk = n & 63;
            float b0v = bias[n], b1v = bias[n + 1];
            if (p < 2) {
                size_t base = ((size_t)(b * H_ + h) * DK_ + dk) * S_;
                Out[base + m]            = acc[mt][nt][0] + b0v;
                Out[base + S_ + m]       = acc[mt][nt][1] + b1v;
                Out[base + m + 8]        = acc[mt][nt][2] + b0v;
                Out[base + S_ + m + 8]   = acc[mt][nt][3] + b1v;
            } else {
                size_t base = ((size_t)(b * H_ + h) * S_ + m) * DK_ + dk;
                Out[base]                = acc[mt][nt][0] + b0v;
                Out[base + 1]            = acc[mt][nt][1] + b1v;
                Out[base + 8 * DK_]      = acc[mt][nt][2] + b0v;
                Out[base + 8 * DK_ + 1]  = acc[mt][nt][3] + b1v;
            }
        }
    }
}

// ---------------- K5: final projection via mma.sync tf32 ----------------
__global__ __launch_bounds__(256) void final_mma(const float* __restrict__ wo,
                                                 const float* __restrict__ bo,
                                                 float* __restrict__ out) {
    extern __shared__ uint32_t smu[];
    int b = blockIdx.z;
    int e = g_sel[b];
    const float* A = g_ctx + (size_t)b * S_ * D_;
    const float* W = wo + (size_t)e * D_ * D_;
    const float* bias = bo + e * D_;
    int bn = blockIdx.x * 128, m0 = blockIdx.y * 128;

    float acc[4][4][4] = {};
    mma_mainloop(smu, A + (size_t)m0 * D_, D_, W, bn, acc);

    const int lane = threadIdx.x & 31, wid = threadIdx.x >> 5;
    const int wm = (wid & 1) * 64, wn = (wid >> 1) * 32;
    const int group = lane >> 2, tig = lane & 3;

#pragma unroll
    for (int mt = 0; mt < 4; mt++) {
#pragma unroll
        for (int nt = 0; nt < 4; nt++) {
            int n = bn + wn + nt * 8 + 2 * tig;
            int m = m0 + wm + mt * 16 + group;
            float b0v = bias[n], b1v = bias[n + 1];
            float* d0 = out + ((size_t)b * S_ + m) * D_ + n;
            d0[0]            = acc[mt][nt][0] + b0v;
            d0[1]            = acc[mt][nt][1] + b1v;
            d0[8 * D_]       = acc[mt][nt][2] + b0v;
            d0[8 * D_ + 1]   = acc[mt][nt][3] + b1v;
        }
    }
}

// ---------------- K4: fused attention, 1024 blocks (b,h,qt of 32 rows), streamed K/V ----------------
// smem floats: Qt[64dk][32q] @0 (2048) | Buf0 @2048 | Buf1 @6144 (each 64x64) | Ps[32q][256] @10240
// total 18432 floats = 73728 B -> 3 CTAs/SM
#define ATTN_SMEM_BYTES (18432 * 4)

__global__ __launch_bounds__(256, 3) void fused_attn_kernel(const int* __restrict__ mask) {
    extern __shared__ float smf[];
    float* Qt = smf;
    float* Ps = smf + 10240;

    int z = blockIdx.x;                 // 1024 blocks
    int bh = z >> 3, qt = z & 7;
    int b = bh >> 3, h = bh & 7;
    int tid = threadIdx.x;
    int warp = tid >> 5, lane = tid & 31;

    const float* ksrc = g_kh + (size_t)bh * 16384;   // [dk][256]
    const float* vsrc = g_vh + (size_t)bh * 16384;   // [256][64]
    const float* qsrc = g_qh + (size_t)bh * 16384 + qt * 32;

    // load Qt[dk][0..31] : 512 float4, 2 per thread
    {
#pragma unroll
        for (int j = 0; j < 2; j++) {
            int lin = tid + j * 256;
            int dk = lin >> 3, c = (lin & 7) * 4;
            *(float4*)&Qt[dk * 32 + c] = *(const float4*)(qsrc + (size_t)dk * S_ + c);
        }
    }

    // preload K chunk 0 into Buf0
    {
        float* dst = smf + 2048;
#pragma unroll
        for (int j = 0; j < 4; j++) {
            int lin = tid + j * 256;
            int dk = lin >> 4, c = (lin & 15) * 4;
            *(float4*)&dst[dk * 64 + c] = *(const float4*)(ksrc + (size_t)dk * S_ + c);
        }
    }
    __syncthreads();

    // -------- GEMM1: scores over 4 K-chunks (warp owns rows warp*4..+3) --------
    float pf[4][8];
    for (int ch = 0; ch < 4; ch++) {
        float4 nx[4];
        if (ch < 3) {
#pragma unroll
            for (int j = 0; j < 4; j++) {
                int lin = tid + j * 256;
                int dk = lin >> 4, c = (lin & 15) * 4;
                nx[j] = *(const float4*)(ksrc + (size_t)dk * S_ + (ch + 1) * 64 + c);
            }
        }
        const float* cur = smf + 2048 + (ch & 1) * 4096;

        uint64_t pch[4] = {};
        {
            float4 x0 = *(const float4*)&Qt[warp * 4];
            uint64_t kk = *(const uint64_t*)&cur[lane * 2];
#pragma unroll 8
            for (int dk = 0; dk < 64; dk++) {
                float a[4] = {x0.x, x0.y, x0.z, x0.w};
                uint64_t kc = kk;
                if (dk < 63) {
                    x0 = *(const float4*)&Qt[(dk + 1) * 32 + warp * 4];
                    kk = *(const uint64_t*)&cur[(dk + 1) * 64 + lane * 2];
                }
#pragma unroll
                for (int i = 0; i < 4; i++) fma2(pch[i], bcast2(a[i]), kc);
            }
        }
#pragma unroll
        for (int i = 0; i < 4; i++) {
            float2 f = unpack2(pch[i]);
            pf[i][2 * ch]     = f.x;
            pf[i][2 * ch + 1] = f.y;
        }

        if (ch < 3) {
            float* nb = smf + 2048 + ((ch + 1) & 1) * 4096;
#pragma unroll
            for (int j = 0; j < 4; j++) {
                int lin = tid + j * 256;
                int dk = lin >> 4, c = (lin & 15) * 4;
                *(float4*)&nb[dk * 64 + c] = nx[j];
            }
        }
        __syncthreads();
    }

    // -------- mask + softmax (row = warp; lane owns cols ch*64+lane*2+{0,1}) --------
#pragma unroll
    for (int i = 0; i < 4; i++) {
        int r = qt * 32 + warp * 4 + i;
#pragma unroll
        for (int c = 0; c < 4; c++) {
            int2 mm = *(const int2*)&mask[r * S_ + c * 64 + lane * 2];
            pf[i][2 * c]     = (mm.x == 0) ? -1e9f : pf[i][2 * c]     * 0.125f;
            pf[i][2 * c + 1] = (mm.y == 0) ? -1e9f : pf[i][2 * c + 1] * 0.125f;
        }
        float mx = pf[i][0];
#pragma unroll
        for (int j = 1; j < 8; j++) mx = fmaxf(mx, pf[i][j]);
#pragma unroll
        for (int off = 16; off > 0; off >>= 1)
            mx = fmaxf(mx, __shfl_xor_sync(0xffffffffu, mx, off));
        float sum = 0.0f;
#pragma unroll
        for (int j = 0; j < 8; j++) { pf[i][j] = __expf(pf[i][j] - mx); sum += pf[i][j]; }
#pragma unroll
        for (int off = 16; off > 0; off >>= 1)
            sum += __shfl_xor_sync(0xffffffffu, sum, off);
        float inv = 1.0f / sum;
#pragma unroll
        for (int j = 0; j < 8; j++) pf[i][j] *= inv;
    }

    // write Ps[row][col]
#pragma unroll
    for (int i = 0; i < 4; i++) {
        int row = warp * 4 + i;
#pragma unroll
        for (int c = 0; c < 4; c++) {
            *(float2*)&Ps[row * 256 + c * 64 + lane * 2] =
                make_float2(pf[i][2 * c], pf[i][2 * c + 1]);
        }
    }

    // preload V chunk 0 into Buf0 (contiguous copy)
    {
        float4* dst = (float4*)(smf + 2048);
        const float4* src = (const float4*)vsrc;
#pragma unroll
        for (int j = 0; j < 4; j++) dst[tid + j * 256] = src[tid + j * 256];
    }
    __syncthreads();

    // -------- GEMM2: ctx(32x64) = Ps @ V over 4 V-chunks; thread: 2 rows x 4 dk --------
    const int ty2 = tid >> 4, tx2 = tid & 15;
    uint64_t c2p[2][2] = {};
    for (int ch = 0; ch < 4; ch++) {
        float4 nv[4];
        if (ch < 3) {
            const float4* src = (const float4*)(vsrc + (ch + 1) * 4096);
#pragma unroll
            for (int j = 0; j < 4; j++) nv[j] = src[tid + j * 256];
        }
        const float* Vb = smf + 2048 + (ch & 1) * 4096;   // [64 rows][64 dk]

        {
            float4 av[2][2];
            uint64_t bvu[2][4][2];
#pragma unroll
            for (int i = 0; i < 2; i++)
                av[0][i] = *(const float4*)&Ps[(ty2 * 2 + i) * 256 + ch * 64];
#pragma unroll
            for (int t = 0; t < 4; t++) {
                const uint64_t* vp = (const uint64_t*)&Vb[t * 64 + tx2 * 4];
                bvu[0][t][0] = vp[0]; bvu[0][t][1] = vp[1];
            }
#pragma unroll 2
            for (int kc = 0; kc < 64; kc += 4) {
                int curb = (kc >> 2) & 1, nxt = curb ^ 1;
                if (kc < 60) {
#pragma unroll
                    for (int i = 0; i < 2; i++)
                        av[nxt][i] = *(const float4*)&Ps[(ty2 * 2 + i) * 256 + ch * 64 + kc + 4];
#pragma unroll
                    for (int t = 0; t < 4; t++) {
                        const uint64_t* vp = (const uint64_t*)&Vb[(kc + 4 + t) * 64 + tx2 * 4];
                        bvu[nxt][t][0] = vp[0]; bvu[nxt][t][1] = vp[1];
                    }
                }
#pragma unroll
                for (int t = 0; t < 4; t++) {
#pragma unroll
                    for (int i = 0; i < 2; i++) {
                        uint64_t ap = bcast2(getf4(av[curb][i], t));
                        fma2(c2p[i][0], ap, bvu[curb][t][0]);
                        fma2(c2p[i][1], ap, bvu[curb][t][1]);
                    }
                }
            }
        }

        if (ch < 3) {
            float* nb = smf + 2048 + ((ch + 1) & 1) * 4096;
            float4* dst = (float4*)nb;
#pragma unroll
            for (int j = 0; j < 4; j++) dst[tid + j * 256] = nv[j];
        }
        __syncthreads();
    }

    // write ctx
#pragma unroll
    for (int i = 0; i < 2; i++) {
        int s = qt * 32 + ty2 * 2 + i;
        float2 lo = unpack2(c2p[i][0]);
        float2 hi = unpack2(c2p[i][1]);
        *(float4*)&g_ctx[((size_t)b * S_ + s) * D_ + h * DK_ + tx2 * 4] =
            make_float4(lo.x, lo.y, hi.x, hi.y);
    }
}

// ---------------- launch ----------------
extern "C" void kernel_launch(void* const* d_in, const int* in_sizes, int n_in,
                              void* d_out, int out_size) {
    const float* q    = (const float*)d_in[0];
    const float* k    = (const float*)d_in[1];
    const float* v    = (const float*)d_in[2];
    const int*   mask = (const int*)  d_in[3];
    const float* wg   = (const float*)d_in[4];
    const float* wn   = (const float*)d_in[5];
    const float* wq   = (const float*)d_in[6];
    const float* bq   = (const float*)d_in[7];
    const float* wk   = (const float*)d_in[8];
    const float* bk   = (const float*)d_in[9];
    const float* wv   = (const float*)d_in[10];
    const float* bv   = (const float*)d_in[11];
    const float* wo   = (const float*)d_in[12];
    const float* bo   = (const float*)d_in[13];
    float* out = (float*)d_out;

    cudaFuncSetAttribute(fused_attn_kernel,
                         cudaFuncAttributeMaxDynamicSharedMemorySize, ATTN_SMEM_BYTES);
    cudaFuncSetAttribute(proj_mma,
                         cudaFuncAttributeMaxDynamicSharedMemorySize, MMA_SMEM_BYTES);
    cudaFuncSetAttribute(final_mma,
                         cudaFuncAttributeMaxDynamicSharedMemorySize, MMA_SMEM_BYTES);

    xsum_kernel<<<B_, 512>>>(q);
    gating_kernel<<<1, 1024>>>(wg, wn, out, out_size);
    proj_mma<<<dim3(4, 2, B_ * 3), 256, MMA_SMEM_BYTES>>>(q, k, v, wq, wk, wv, bq, bk, bv);
    fused_attn_kernel<<<B_ * H_ * 8, 256, ATTN_SMEM_BYTES>>>(mask);
    final_mma<<<dim3(4, 2, B_), 256, MMA_SMEM_BYTES>>>(wo, bo, out);
}

// round 12
// speedup vs baseline: 1.1576x; 1.0895x over previous
#include <cuda_runtime.h>
#include <cstdint>

#define E_  8
#define H_  8
#define D_  512
#define B_  16
#define S_  256
#define DK_ 64

// ---------------- scratch ----------------
__device__ float g_xsum[B_ * D_];
__device__ int   g_sel[B_];
__device__ float g_qh[B_ * H_ * DK_ * S_];          // [b][h][dk][s]
__device__ float g_kh[B_ * H_ * DK_ * S_];          // [b][h][dk][kcol]
__device__ float g_vh[B_ * H_ * S_ * DK_];          // [b][h][s][dk]
__device__ float g_ctx[B_ * S_ * D_];

// ---------------- helpers ----------------
__device__ __forceinline__ uint32_t f2tf32(float x) {
    uint32_t r;
    asm("cvt.rna.tf32.f32 %0, %1;" : "=r"(r) : "f"(x));
    return r;
}

__device__ __forceinline__ void mma_tf32(float* c, const uint32_t* a, const uint32_t* b) {
    asm volatile(
        "mma.sync.aligned.m16n8k8.row.col.f32.tf32.tf32.f32 "
        "{%0,%1,%2,%3}, {%4,%5,%6,%7}, {%8,%9}, {%0,%1,%2,%3};"
        : "+f"(c[0]), "+f"(c[1]), "+f"(c[2]), "+f"(c[3])
        : "r"(a[0]), "r"(a[1]), "r"(a[2]), "r"(a[3]), "r"(b[0]), "r"(b[1]));
}

// packed fp32x2 (Blackwell FFMA2)
__device__ __forceinline__ uint64_t bcast2(float v) {
    uint64_t r;
    asm("mov.b64 %0, {%1,%1};" : "=l"(r) : "f"(v));
    return r;
}
__device__ __forceinline__ void fma2(uint64_t& c, uint64_t a, uint64_t b) {
    asm("fma.rn.f32x2 %0, %1, %2, %0;" : "+l"(c) : "l"(a), "l"(b));
}
__device__ __forceinline__ float2 unpack2(uint64_t v) {
    float2 f;
    asm("mov.b64 {%0,%1}, %2;" : "=f"(f.x), "=f"(f.y) : "l"(v));
    return f;
}
__device__ __forceinline__ float getf4(float4 v, int t) {
    switch (t) {
        case 0: return v.x;
        case 1: return v.y;
        case 2: return v.z;
        default: return v.w;
    }
}

// ---------------- threefry2x32 (JAX partitionable, key=(0,42)) ----------------
__device__ __forceinline__ uint32_t rotl32(uint32_t x, int r) {
    return (x << r) | (x >> (32 - r));
}
__device__ void threefry2x32(uint32_t k0, uint32_t k1, uint32_t c0, uint32_t c1,
                             uint32_t* o0, uint32_t* o1) {
    uint32_t ks2 = k0 ^ k1 ^ 0x1BD11BDAu;
    uint32_t x0 = c0 + k0;
    uint32_t x1 = c1 + k1;
    const int R0[4] = {13, 15, 26, 6};
    const int R1[4] = {17, 29, 16, 24};
#pragma unroll
    for (int i = 0; i < 4; i++) { x0 += x1; x1 = rotl32(x1, R0[i]); x1 ^= x0; }
    x0 += k1;  x1 += ks2 + 1u;
#pragma unroll
    for (int i = 0; i < 4; i++) { x0 += x1; x1 = rotl32(x1, R1[i]); x1 ^= x0; }
    x0 += ks2; x1 += k0 + 2u;
#pragma unroll
    for (int i = 0; i < 4; i++) { x0 += x1; x1 = rotl32(x1, R0[i]); x1 ^= x0; }
    x0 += k0;  x1 += k1 + 3u;
#pragma unroll
    for (int i = 0; i < 4; i++) { x0 += x1; x1 = rotl32(x1, R1[i]); x1 ^= x0; }
    x0 += k1;  x1 += ks2 + 4u;
#pragma unroll
    for (int i = 0; i < 4; i++) { x0 += x1; x1 = rotl32(x1, R0[i]); x1 ^= x0; }
    x0 += ks2; x1 += k0 + 5u;
    *o0 = x0; *o1 = x1;
}

__device__ float erfinv_xla(float x) {
    float w = -log1pf(-x * x);
    float p;
    if (w < 5.0f) {
        w -= 2.5f;
        p = 2.81022636e-08f;
        p = fmaf(p, w, 3.43273939e-07f);
        p = fmaf(p, w, -3.5233877e-06f);
        p = fmaf(p, w, -4.39150654e-06f);
        p = fmaf(p, w, 0.00021858087f);
        p = fmaf(p, w, -0.00125372503f);
        p = fmaf(p, w, -0.00417768164f);
        p = fmaf(p, w, 0.246640727f);
        p = fmaf(p, w, 1.50140941f);
    } else {
        w = sqrtf(w) - 3.0f;
        p = -0.000200214257f;
        p = fmaf(p, w, 0.000100950558f);
        p = fmaf(p, w, 0.00134934322f);
        p = fmaf(p, w, -0.00367342844f);
        p = fmaf(p, w, 0.00573950773f);
        p = fmaf(p, w, -0.0076224613f);
        p = fmaf(p, w, 0.00943887047f);
        p = fmaf(p, w, 1.00167406f);
        p = fmaf(p, w, 2.83297682f);
    }
    return p * x;
}

// ---------------- K1: full xsum ----------------
__global__ void xsum_kernel(const float* __restrict__ q) {
    int b = blockIdx.x, d = threadIdx.x;
    const float* p = q + (size_t)b * S_ * D_ + d;
    float acc = 0.0f;
#pragma unroll 16
    for (int s = 0; s < S_; s++) acc += p[s * D_];
    g_xsum[b * D_ + d] = acc;
}

// ---------------- K2: gating (1024 threads, sliced dot products) ----------------
__global__ __launch_bounds__(1024) void gating_kernel(const float* __restrict__ wg,
                                                      const float* __restrict__ wn,
                                                      float* __restrict__ d_out,
                                                      int out_size) {
    int tid = threadIdx.x;
    int be = tid & 127, slice = tid >> 7;
    int b = be >> 3, e = be & 7;

    float clp = 0.0f, rnp = 0.0f;
#pragma unroll 8
    for (int i = slice * 64; i < slice * 64 + 64; i++) {
        float xs = g_xsum[b * D_ + i];
        clp = fmaf(xs, wg[i * E_ + e], clp);
        rnp = fmaf(xs, wn[i * E_ + e], rnp);
    }

    __shared__ float scl[8][128], srn[8][128];
    __shared__ float s_noisy[128], s_thrin[B_], s_throut[B_];
    __shared__ float s_load[E_], s_imp[E_];
    scl[slice][be] = clp; srn[slice][be] = rnp;
    if (tid < E_) { s_load[tid] = 0.0f; s_imp[tid] = 0.0f; }
    __syncthreads();

    float cl = 0.0f, rn = 0.0f, stdv = 1.0f, noisy = 0.0f;
    if (tid < 128) {
#pragma unroll
        for (int s = 0; s < 8; s++) { cl += scl[s][tid]; rn += srn[s][tid]; }

        float sp = fmaxf(rn, 0.0f) + log1pf(expf(-fabsf(rn)));
        stdv = sp + 0.01f;

        uint32_t o0, o1;
        threefry2x32(0u, 42u, 0u, (uint32_t)tid, &o0, &o1);
        uint32_t bits = o0 ^ o1;
        uint32_t fb = (bits >> 9) | 0x3f800000u;
        float f = __uint_as_float(fb) - 1.0f;
        float u = f * 2.0f + (-0.99999994f);
        u = fmaxf(-0.99999994f, u);
        float z = 1.41421354f * erfinv_xla(u);
        noisy = cl + z * stdv;
        s_noisy[tid] = noisy;
    }
    __syncthreads();

    if (tid < B_) {
        float m1 = -3.0e38f, m2 = -3.0e38f;
        int i1 = 0;
        for (int ee = 0; ee < E_; ee++) {
            float val = s_noisy[tid * 8 + ee];
            if (val > m1) { m2 = m1; m1 = val; i1 = ee; }
            else if (val > m2) { m2 = val; }
        }
        g_sel[tid] = i1;
        s_thrin[tid] = m2;
        s_throut[tid] = m1;
        atomicAdd(&s_imp[i1], 1.0f);
    }
    __syncthreads();

    if (tid < 128) {
        float thr = (noisy > s_thrin[b]) ? s_thrin[b] : s_throut[b];
        float arg = ((cl - thr) / stdv) / 1.41421354f;
        float ph = 0.5f * (1.0f + erff(arg));
        atomicAdd(&s_load[e], ph);
    }
    __syncthreads();

    if (tid == 0) {
        auto cv2 = [](const float* x) {
            float mean = 0.0f;
            for (int i = 0; i < E_; i++) mean += x[i];
            mean *= (1.0f / E_);
            float var = 0.0f;
            for (int i = 0; i < E_; i++) { float d = x[i] - mean; var += d * d; }
            var *= (1.0f / (E_ - 1));
            return var / (mean * mean + 1e-10f);
        };
        float loss = 0.01f * (cv2(s_imp) + cv2(s_load));
        if (out_size > B_ * S_ * D_) d_out[B_ * S_ * D_] = loss;
    }
}

// ---------------- tf32 mma.sync mainloop (128x128 block, K=512) ----------------
// SINGLE smem buffer (A @0 stride 36, B @4608 stride 132) => 34.5 KB => 2 CTAs/SM.
// Cross-CTA overlap replaces double buffering; next K-panel is prefetched in regs.
#define SA_ 36
#define SB_ 132
#define MMA_SMEM_BYTES ((4608 + 4224) * 4)

__device__ __forceinline__ void mma_mainloop(
        uint32_t* sm, const float* __restrict__ A, int lda,
        const float* __restrict__ W, int n0, float acc[4][4][4]) {
    const int tid = threadIdx.x;
    const int wid = tid >> 5, lane = tid & 31;
    const int wm = (wid & 1) * 64, wn = (wid >> 1) * 32;
    const int group = lane >> 2, tig = lane & 3;

    const int arow = tid >> 1, acol = (tid & 1) * 16;
    const int brow = tid >> 3, bcol = (tid & 7) * 16;

    uint32_t* da = sm + arow * SA_ + acol;
    uint32_t* db = sm + 4608 + brow * SB_ + bcol;
    const uint32_t* As = sm;
    const uint32_t* Bs = sm + 4608;

    float4 ar[4], br[4];
#pragma unroll
    for (int i = 0; i < 4; i++) {
        ar[i] = *(const float4*)(A + (size_t)arow * lda + acol + 4 * i);
        br[i] = *(const float4*)(W + (size_t)brow * D_ + n0 + bcol + 4 * i);
    }
#pragma unroll
    for (int i = 0; i < 4; i++) {
        da[4*i+0] = f2tf32(ar[i].x); da[4*i+1] = f2tf32(ar[i].y);
        da[4*i+2] = f2tf32(ar[i].z); da[4*i+3] = f2tf32(ar[i].w);
        db[4*i+0] = f2tf32(br[i].x); db[4*i+1] = f2tf32(br[i].y);
        db[4*i+2] = f2tf32(br[i].z); db[4*i+3] = f2tf32(br[i].w);
    }
    __syncthreads();

    for (int t = 0; t < 16; t++) {
        if (t < 15) {
            int kb = (t + 1) * 32;
#pragma unroll
            for (int i = 0; i < 4; i++) {
                ar[i] = *(const float4*)(A + (size_t)arow * lda + kb + acol + 4 * i);
                br[i] = *(const float4*)(W + (size_t)(kb + brow) * D_ + n0 + bcol + 4 * i);
            }
        }
#pragma unroll
        for (int ks = 0; ks < 4; ks++) {
            int k0 = ks * 8;
            uint32_t af[4][4], bf[4][2];
#pragma unroll
            for (int mt = 0; mt < 4; mt++) {
                int r0 = wm + mt * 16 + group;
                af[mt][0] = As[r0 * SA_ + k0 + tig];
                af[mt][1] = As[(r0 + 8) * SA_ + k0 + tig];
                af[mt][2] = As[r0 * SA_ + k0 + tig + 4];
                af[mt][3] = As[(r0 + 8) * SA_ + k0 + tig + 4];
            }
#pragma unroll
            for (int nt = 0; nt < 4; nt++) {
                int c0 = wn + nt * 8 + group;
                bf[nt][0] = Bs[(k0 + tig) * SB_ + c0];
                bf[nt][1] = Bs[(k0 + tig + 4) * SB_ + c0];
            }
#pragma unroll
            for (int mt = 0; mt < 4; mt++)
#pragma unroll
                for (int nt = 0; nt < 4; nt++)
                    mma_tf32(acc[mt][nt], af[mt], bf[nt]);
        }
        if (t < 15) {
            __syncthreads();   // all reads of the buffer complete
#pragma unroll
            for (int i = 0; i < 4; i++) {
                da[4*i+0] = f2tf32(ar[i].x); da[4*i+1] = f2tf32(ar[i].y);
                da[4*i+2] = f2tf32(ar[i].z); da[4*i+3] = f2tf32(ar[i].w);
                db[4*i+0] = f2tf32(br[i].x); db[4*i+1] = f2tf32(br[i].y);
                db[4*i+2] = f2tf32(br[i].z); db[4*i+3] = f2tf32(br[i].w);
            }
            __syncthreads();   // buffer refilled
        }
    }
}

// ---------------- K3: projections via mma.sync tf32 ----------------
__global__ __launch_bounds__(256, 2) void proj_mma(
        const float* __restrict__ q, const float* __restrict__ k,
        const float* __restrict__ v,
        const float* __restrict__ wq, const float* __restrict__ wk,
        const float* __restrict__ wv,
        const float* __restrict__ bq, const float* __restrict__ bk,
        const float* __restrict__ bv) {
    extern __shared__ uint32_t smu[];
    int z = blockIdx.z;
    int b = z / 3, p = z % 3;
    int e = g_sel[b];
    const float* X = (p == 0 ? q : (p == 1 ? k : v)) + (size_t)b * S_ * D_;
    const float* W = (p == 0 ? wq : (p == 1 ? wk : wv)) + (size_t)e * D_ * D_;
    const float* bias = (p == 0 ? bq : (p == 1 ? bk : bv)) + e * D_;
    float* Out = (p == 0 ? g_qh : (p == 1 ? g_kh : g_vh));
    int bn = blockIdx.x * 128, m0 = blockIdx.y * 128;

    float acc[4][4][4] = {};
    mma_mainloop(smu, X + (size_t)m0 * D_, D_, W, bn, acc);

    const int lane = threadIdx.x & 31, wid = threadIdx.x >> 5;
    const int wm = (wid & 1) * 64, wn = (wid >> 1) * 32;
    const int group = lane >> 2, tig = lane & 3;

#pragma unroll
    for (int mt = 0; mt < 4; mt++) {
#pragma unroll
        for (int nt = 0; nt < 4; nt++) {
            int n = bn + wn + nt * 8 + 2 * tig;
            int m = m0 + wm + mt * 16 + group;
            int h = n >> 6, dk = n & 63;
            float b0v = bias[n], b1v = bias[n + 1];
            if (p < 2) {
                size_t base = ((size_t)(b * H_ + h) * DK_ + dk) * S_;
                Out[base + m]            = acc[mt][nt][0] + b0v;
                Out[base + S_ + m]       = acc[mt][nt][1] + b1v;
                Out[base + m + 8]        = acc[mt][nt][2] + b0v;
                Out[base + S_ + m + 8]   = acc[mt][nt][3] + b1v;
            } else {
                size_t base = ((size_t)(b * H_ + h) * S_ + m) * DK_ + dk;
                Out[base]                = acc[mt][nt][0] + b0v;
                Out[base + 1]            = acc[mt][nt][1] + b1v;
                Out[base + 8 * DK_]      = acc[mt][nt][2] + b0v;
                Out[base + 8 * DK_ + 1]  = acc[mt][nt][3] + b1v;
            }
        }
    }
}

// ---------------- K5: final projection via mma.sync tf32 ----------------
__global__ __launch_bounds__(256, 2) void final_mma(const float* __restrict__ wo,
                                                    const float* __restrict__ bo,
                                                    float* __restrict__ out) {
    extern __shared__ uint32_t smu[];
    int b = blockIdx.z;
    int e = g_sel[b];
    const float* A = g_ctx + (size_t)b * S_ * D_;
    const float* W = wo + (size_t)e * D_ * D_;
    const float* bias = bo + e * D_;
    int bn = blockIdx.x * 128, m0 = blockIdx.y * 128;

    float acc[4][4][4] = {};
    mma_mainloop(smu, A + (size_t)m0 * D_, D_, W, bn, acc);

    const int lane = threadIdx.x & 31, wid = threadIdx.x >> 5;
    const int wm = (wid & 1) * 64, wn = (wid >> 1) * 32;
    const int group = lane >> 2, tig = lane & 3;

#pragma unroll
    for (int mt = 0; mt < 4; mt++) {
#pragma unroll
        for (int nt = 0; nt < 4; nt++) {
            int n = bn + wn + nt * 8 + 2 * tig;
            int m = m0 + wm + mt * 16 + group;
            float b0v = bias[n], b1v = bias[n + 1];
            float* d0 = out + ((size_t)b * S_ + m) * D_ + n;
            d0[0]            = acc[mt][nt][0] + b0v;
            d0[1]            = acc[mt][nt][1] + b1v;
            d0[8 * D_]       = acc[mt][nt][2] + b0v;
            d0[8 * D_ + 1]   = acc[mt][nt][3] + b1v;
        }
    }
}

// ---------------- K4: fused attention (R9 config: 512 blocks, 64-row q-tiles) ----------------
// smem floats: Qt[64dk][64q] @0 | Buf0 @4096 | Buf1 @8192 (each 64x64) | Ps[64q][256] @12288
#define ATTN_SMEM_BYTES (28672 * 4)

__global__ __launch_bounds__(256, 2) void fused_attn_kernel(const int* __restrict__ mask) {
    extern __shared__ float smf[];
    float* Qt = smf;
    float* Ps = smf + 12288;

    int z = blockIdx.x;                 // 512 blocks
    int bh = z >> 2, qt = z & 3;
    int b = bh >> 3, h = bh & 7;
    int tid = threadIdx.x;
    int warp = tid >> 5, lane = tid & 31;

    const float* ksrc = g_kh + (size_t)bh * 16384;   // [dk][256]
    const float* vsrc = g_vh + (size_t)bh * 16384;   // [256][64]
    const float* qsrc = g_qh + (size_t)bh * 16384 + qt * 64;

    // load Qt[dk][0..63]
    {
#pragma unroll
        for (int j = 0; j < 4; j++) {
            int lin = tid + j * 256;
            int dk = lin >> 4, c = (lin & 15) * 4;
            *(float4*)&Qt[dk * 64 + c] = *(const float4*)(qsrc + (size_t)dk * S_ + c);
        }
    }

    // preload K chunk 0 into Buf0
    {
        float* dst = smf + 4096;
#pragma unroll
        for (int j = 0; j < 4; j++) {
            int lin = tid + j * 256;
            int dk = lin >> 4, c = (lin & 15) * 4;
            *(float4*)&dst[dk * 64 + c] = *(const float4*)(ksrc + (size_t)dk * S_ + c);
        }
    }
    __syncthreads();

    // -------- GEMM1: scores over 4 K-chunks --------
    float pf[8][8];
    for (int ch = 0; ch < 4; ch++) {
        float4 nx[4];
        if (ch < 3) {
#pragma unroll
            for (int j = 0; j < 4; j++) {
                int lin = tid + j * 256;
                int dk = lin >> 4, c = (lin & 15) * 4;
                nx[j] = *(const float4*)(ksrc + (size_t)dk * S_ + (ch + 1) * 64 + c);
            }
        }
        const float* cur = smf + 4096 + (ch & 1) * 4096;

        uint64_t pch[8] = {};
        {
            float4 x0 = *(const float4*)&Qt[warp * 8];
            float4 x1 = *(const float4*)&Qt[warp * 8 + 4];
            uint64_t kk = *(const uint64_t*)&cur[lane * 2];
#pragma unroll 8
            for (int dk = 0; dk < 64; dk++) {
                float a[8] = {x0.x, x0.y, x0.z, x0.w, x1.x, x1.y, x1.z, x1.w};
                uint64_t kc = kk;
                if (dk < 63) {
                    x0 = *(const float4*)&Qt[(dk + 1) * 64 + warp * 8];
                    x1 = *(const float4*)&Qt[(dk + 1) * 64 + warp * 8 + 4];
                    kk = *(const uint64_t*)&cur[(dk + 1) * 64 + lane * 2];
                }
#pragma unroll
                for (int i = 0; i < 8; i++) fma2(pch[i], bcast2(a[i]), kc);
            }
        }
#pragma unroll
        for (int i = 0; i < 8; i++) {
            float2 f = unpack2(pch[i]);
            pf[i][2 * ch]     = f.x;
            pf[i][2 * ch + 1] = f.y;
        }

        if (ch < 3) {
            float* nb = smf + 4096 + ((ch + 1) & 1) * 4096;
#pragma unroll
            for (int j = 0; j < 4; j++) {
                int lin = tid + j * 256;
                int dk = lin >> 4, c = (lin & 15) * 4;
                *(float4*)&nb[dk * 64 + c] = nx[j];
            }
        }
        __syncthreads();
    }

    // -------- mask + softmax (row = warp; lane owns cols ch*64+lane*2+{0,1}) --------
#pragma unroll
    for (int i = 0; i < 8; i++) {
        int r = qt * 64 + warp * 8 + i;
#pragma unroll
        for (int c = 0; c < 4; c++) {
            int2 mm = *(const int2*)&mask[r * S_ + c * 64 + lane * 2];
            pf[i][2 * c]     = (mm.x == 0) ? -1e9f : pf[i][2 * c]     * 0.125f;
            pf[i][2 * c + 1] = (mm.y == 0) ? -1e9f : pf[i][2 * c + 1] * 0.125f;
        }
        float mx = pf[i][0];
#pragma unroll
        for (int j = 1; j < 8; j++) mx = fmaxf(mx, pf[i][j]);
#pragma unroll
        for (int off = 16; off > 0; off >>= 1)
            mx = fmaxf(mx, __shfl_xor_sync(0xffffffffu, mx, off));
        float sum = 0.0f;
#pragma unroll
        for (int j = 0; j < 8; j++) { pf[i][j] = __expf(pf[i][j] - mx); sum += pf[i][j]; }
#pragma unroll
        for (int off = 16; off > 0; off >>= 1)
            sum += __shfl_xor_sync(0xffffffffu, sum, off);
        float inv = 1.0f / sum;
#pragma unroll
        for (int j = 0; j < 8; j++) pf[i][j] *= inv;
    }

    // write Ps[row][col]
#pragma unroll
    for (int i = 0; i < 8; i++) {
        int row = warp * 8 + i;
#pragma unroll
        for (int c = 0; c < 4; c++) {
            *(float2*)&Ps[row * 256 + c * 64 + lane * 2] =
                make_float2(pf[i][2 * c], pf[i][2 * c + 1]);
        }
    }

    // preload V chunk 0 into Buf0 (contiguous copy)
    {
        float4* dst = (float4*)(smf + 4096);
        const float4* src = (const float4*)vsrc;
#pragma unroll
        for (int j = 0; j < 4; j++) dst[tid + j * 256] = src[tid + j * 256];
    }
    __syncthreads();

    // -------- GEMM2: ctx = Ps @ V over 4 V-chunks --------
    const int ty2 = tid >> 4, tx2 = tid & 15;
    uint64_t c2p[4][2] = {};
    for (int ch = 0; ch < 4; ch++) {
        float4 nv[4];
        if (ch < 3) {
            const float4* src = (const float4*)(vsrc + (ch + 1) * 4096);
#pragma unroll
            for (int j = 0; j < 4; j++) nv[j] = src[tid + j * 256];
        }
        const float* Vb = smf + 4096 + (ch & 1) * 4096;   // [64 rows][64 dk]

        {
            float4 av[2][4];
            uint64_t bvu[2][4][2];
#pragma unroll
            for (int i = 0; i < 4; i++)
                av[0][i] = *(const float4*)&Ps[(ty2 * 4 + i) * 256 + ch * 64];
#pragma unroll
            for (int t = 0; t < 4; t++) {
                const uint64_t* vp = (const uint64_t*)&Vb[t * 64 + tx2 * 4];
                bvu[0][t][0] = vp[0]; bvu[0][t][1] = vp[1];
            }
#pragma unroll 2
            for (int kc = 0; kc < 64; kc += 4) {
                int curb = (kc >> 2) & 1, nxt = curb ^ 1;
                if (kc < 60) {
#pragma unroll
                    for (int i = 0; i < 4; i++)
                        av[nxt][i] = *(const float4*)&Ps[(ty2 * 4 + i) * 256 + ch * 64 + kc + 4];
#pragma unroll
                    for (int t = 0; t < 4; t++) {
                        const uint64_t* vp = (const uint64_t*)&Vb[(kc + 4 + t) * 64 + tx2 * 4];
                        bvu[nxt][t][0] = vp[0]; bvu[nxt][t][1] = vp[1];
                    }
                }
#pragma unroll
                for (int t = 0; t < 4; t++) {
#pragma unroll
                    for (int i = 0; i < 4; i++) {
                        uint64_t ap = bcast2(getf4(av[curb][i], t));
                        fma2(c2p[i][0], ap, bvu[curb][t][0]);
                        fma2(c2p[i][1], ap, bvu[curb][t][1]);
                    }
                }
            }
        }

        if (ch < 3) {
            float* nb = smf + 4096 + ((ch + 1) & 1) * 4096;
            float4* dst = (float4*)nb;
#pragma unroll
            for (int j = 0; j < 4; j++) dst[tid + j * 256] = nv[j];
        }
        __syncthreads();
    }

    // write ctx
#pragma unroll
    for (int i = 0; i < 4; i++) {
        int s = qt * 64 + ty2 * 4 + i;
        float2 lo = unpack2(c2p[i][0]);
        float2 hi = unpack2(c2p[i][1]);
        *(float4*)&g_ctx[((size_t)b * S_ + s) * D_ + h * DK_ + tx2 * 4] =
            make_float4(lo.x, lo.y, hi.x, hi.y);
    }
}

// ---------------- launch ----------------
extern "C" void kernel_launch(void* const* d_in, const int* in_sizes, int n_in,
                              void* d_out, int out_size) {
    const float* q    = (const float*)d_in[0];
    const float* k    = (const float*)d_in[1];
    const float* v    = (const float*)d_in[2];
    const int*   mask = (const int*)  d_in[3];
    const float* wg   = (const float*)d_in[4];
    const float* wn   = (const float*)d_in[5];
    const float* wq   = (const float*)d_in[6];
    const float* bq   = (const float*)d_in[7];
    const float* wk   = (const float*)d_in[8];
    const float* bk   = (const float*)d_in[9];
    const float* wv   = (const float*)d_in[10];
    const float* bv   = (const float*)d_in[11];
    const float* wo   = (const float*)d_in[12];
    const float* bo   = (const float*)d_in[13];
    float* out = (float*)d_out;

    cudaFuncSetAttribute(fused_attn_kernel,
                         cudaFuncAttributeMaxDynamicSharedMemorySize, ATTN_SMEM_BYTES);
    cudaFuncSetAttribute(proj_mma,
                         cudaFuncAttributeMaxDynamicSharedMemorySize, MMA_SMEM_BYTES);
    cudaFuncSetAttribute(final_mma,
                         cudaFuncAttributeMaxDynamicSharedMemorySize, MMA_SMEM_BYTES);

    xsum_kernel<<<B_, 512>>>(q);
    gating_kernel<<<1, 1024>>>(wg, wn, out, out_size);
    proj_mma<<<dim3(4, 2, B_ * 3), 256, MMA_SMEM_BYTES>>>(q, k, v, wq, wk, wv, bq, bk, bv);
    fused_attn_kernel<<<B_ * H_ * 4, 256, ATTN_SMEM_BYTES>>>(mask);
    final_mma<<<dim3(4, 2, B_), 256, MMA_SMEM_BYTES>>>(wo, bo, out);
}